// round 15
// baseline (speedup 1.0000x reference)
#include <cuda_runtime.h>
#include <cuda_bf16.h>
#include <cstdint>

#define NN 256          // NUM_NEURONS
#define NS 512          // NUM_SAMPLES
#define MAXSP 32        // MAX_SPIKES (rounds)
#define NSTEPS 32       // RK4 steps per round
#define V_RESET 1.0f

__device__ __forceinline__ float sigm(float v) {
    const float e = __expf(-v);
    return __fdividef(1.0f, 1.0f + e);   // MUFU.EX2 + MUFU.RCP path
}

__device__ __forceinline__ void rk4_step(float v, float i, float s,
                                         float ic, float mu1, float mu2, float h,
                                         float& vn, float& in_, float& sn) {
    // k1
    float dv1 = mu1 * (i + ic - v);
    float di1 = -mu2 * i;
    float ds1 = sigm(v);
    // k2
    float v2 = fmaf(0.5f * h, dv1, v);
    float i2 = fmaf(0.5f * h, di1, i);
    float dv2 = mu1 * (i2 + ic - v2);
    float di2 = -mu2 * i2;
    float ds2 = sigm(v2);
    // k3
    float v3 = fmaf(0.5f * h, dv2, v);
    float i3 = fmaf(0.5f * h, di2, i);
    float dv3 = mu1 * (i3 + ic - v3);
    float di3 = -mu2 * i3;
    float ds3 = sigm(v3);
    // k4
    float v4 = fmaf(h, dv3, v);
    float i4 = fmaf(h, di3, i);
    float dv4 = mu1 * (i4 + ic - v4);
    float di4 = -mu2 * i4;
    float ds4 = sigm(v4);

    const float c = h * (1.0f / 6.0f);
    vn  = fmaf(c, dv1 + 2.0f * (dv2 + dv3) + dv4, v);
    in_ = fmaf(c, di1 + 2.0f * (di2 + di3) + di4, i);
    sn  = fmaf(c, ds1 + 2.0f * (ds2 + ds3) + ds4, s);
}

// order-preserving float<->uint maps
__device__ __forceinline__ unsigned f2ord(float x) {
    unsigned u = __float_as_uint(x);
    return (u & 0x80000000u) ? ~u : (u | 0x80000000u);
}
__device__ __forceinline__ float ord2f(unsigned o) {
    unsigned u = (o & 0x80000000u) ? (o & 0x7fffffffu) : ~o;
    return __uint_as_float(u);
}

__global__ __launch_bounds__(NN, 4)
void snn_kernel(const float* __restrict__ ic_g,     // [NN]
                const float* __restrict__ w,        // [NN, NN]
                const float* __restrict__ mu_g,     // [2]
                const float* __restrict__ v0_g,     // [NN]
                const float* __restrict__ i0_g,     // [NN]
                const float* __restrict__ s0_g,     // [NS, NN]
                const float* __restrict__ reset_s,  // [MAXSP, NS, NN]
                const int*   __restrict__ t1_p,     // scalar
                float* __restrict__ out_times,      // [NS, MAXSP]
                float* __restrict__ out_vals,       // [NS, MAXSP, NN, 3]
                float* __restrict__ out_marks)      // [NS, MAXSP, NN]
{
    const int smp = blockIdx.x;
    const int n   = threadIdx.x;

    const float t1f = (float)(*t1_p);
    const float mu1 = mu_g[0];
    const float mu2 = mu_g[1];
    const float ic  = ic_g[n];

    float v = v0_g[n];
    float i = i0_g[n];
    float s = s0_g[(size_t)smp * NN + n];
    float t0 = 0.0f;

    // parity-buffered trigger cells (0 == "no trigger": any crossing key has
    // top bit of ord(sn) set, so key >= 0x80000000_00 > 0)
    __shared__ unsigned long long key_sh[2];
    __shared__ int                eidx_sh[2];
    __shared__ float              s_all[2][NN];  // s_prev published by crossers

    if (n == 0) {
        key_sh[0] = key_sh[1] = 0ull;
        eidx_sh[0] = eidx_sh[1] = NN;
    }
    __syncthreads();

    #pragma unroll 1
    for (int k = 0; k < MAXSP; k++) {
        const float rs = reset_s[((size_t)k * NS + smp) * NN + n];

        const float dt = (t1f - t0) * (1.0f / NSTEPS);
        bool  done = false;
        float tev  = t1f;
        bool  em   = false;
        int   eidx = 0;

        if (dt > 0.0f) {
            // ---- prologue: compute step 0, publish its crossings ----
            float vn, in_, sn;
            rk4_step(v, i, s, ic, mu1, mu2, dt, vn, in_, sn);
            bool cross = sn > 0.0f;
            if (cross) {
                s_all[0][n] = s;
                atomicMax(&key_sh[0],
                          ((unsigned long long)f2ord(sn) << 8)
                          | (unsigned long long)(255 - n));
                atomicMin(&eidx_sh[0], n);
            }

            #pragma unroll 1
            for (int st = 0; st < NSTEPS; st++) {
                const int p = st & 1;
                __syncthreads();   // cell p (step st) fully published

                // ---- speculative step st+1: hides BAR+LDS latency ----
                float vn2, in2, sn2;
                bool cross2 = false;
                if (st + 1 < NSTEPS) {
                    rk4_step(vn, in_, sn, ic, mu1, mu2, dt, vn2, in2, sn2);
                    cross2 = sn2 > 0.0f;
                    if (cross2) {
                        s_all[p ^ 1][n] = sn;
                        atomicMax(&key_sh[p ^ 1],
                                  ((unsigned long long)f2ord(sn2) << 8)
                                  | (unsigned long long)(255 - n));
                        atomicMin(&eidx_sh[p ^ 1], n);
                    }
                }

                const unsigned long long key = key_sh[p];
                if (key) {
                    // ---- trigger at step st (block-uniform) ----
                    em   = cross;
                    eidx = eidx_sh[p];
                    const int   widx = 255 - (int)(key & 0xffull);
                    const float mval = ord2f((unsigned)(key >> 8));
                    const float msp  = s_all[p][widx];

                    float frac = msp / (msp - mval + 1e-12f);
                    frac = fminf(fmaxf(frac, 0.0f), 1.0f);
                    tev = t0 + (float)st * dt + frac * dt;
                    v += frac * (vn - v);
                    i += frac * (in_ - i);
                    s += frac * (sn - s);
                    done = true;

                    __syncthreads();   // all reads of cells complete
                    if (n == 0) {      // reset both (speculative cell polluted)
                        key_sh[0] = key_sh[1] = 0ull;
                        eidx_sh[0] = eidx_sh[1] = NN;
                    }
                    __syncthreads();   // reset visible before next round's publish
                    break;
                }
                // advance pipeline
                v = vn; i = in_; s = sn;
                vn = vn2; in_ = in2; sn = sn2; cross = cross2;
            }
        }

        // ---- outputs (pre-reset event state); tev = t1f if no trigger ----
        const size_t base = ((size_t)smp * MAXSP + k) * NN + n;
        if (n == 0) out_times[smp * MAXSP + k] = tev;
        out_vals[base * 3 + 0] = v;
        out_vals[base * 3 + 1] = i;
        out_vals[base * 3 + 2] = s;
        out_marks[base] = em ? 1.0f : 0.0f;

        // ---- reset & carry ----
        const float wr = done ? w[(size_t)eidx * NN + n] : 0.0f;
        v -= em ? V_RESET : 0.0f;
        i += wr;
        s  = fminf(em ? rs : s, 0.0f);
        t0 = tev;
    }
}

extern "C" void kernel_launch(void* const* d_in, const int* in_sizes, int n_in,
                              void* d_out, int out_size) {
    const float* ic      = (const float*)d_in[0];
    const float* w       = (const float*)d_in[1];
    const float* mu      = (const float*)d_in[2];
    const float* v0      = (const float*)d_in[3];
    const float* i0      = (const float*)d_in[4];
    const float* s0      = (const float*)d_in[5];
    const float* reset_s = (const float*)d_in[6];
    const int*   t1      = (const int*)d_in[7];

    float* out = (float*)d_out;
    float* out_times = out;                                    // NS*MAXSP
    float* out_vals  = out + (size_t)NS * MAXSP;               // NS*MAXSP*NN*3
    float* out_marks = out_vals + (size_t)NS * MAXSP * NN * 3; // NS*MAXSP*NN

    snn_kernel<<<NS, NN>>>(ic, w, mu, v0, i0, s0, reset_s, t1,
                           out_times, out_vals, out_marks);
}

// round 16
// speedup vs baseline: 1.1096x; 1.1096x over previous
#include <cuda_runtime.h>
#include <cuda_bf16.h>
#include <cstdint>

#define NN 256          // NUM_NEURONS
#define NS 512          // NUM_SAMPLES
#define MAXSP 32        // MAX_SPIKES (rounds)
#define NSTEPS 32       // RK4 steps per round
#define V_RESET 1.0f
#define NT 128          // threads per block (2 neurons each)

__device__ __forceinline__ float sigm(float v) {
    const float e = __expf(-v);
    return __fdividef(1.0f, 1.0f + e);   // MUFU.EX2 + MUFU.RCP path
}

__device__ __forceinline__ void rk4_step(float v, float i, float s,
                                         float ic, float mu1, float mu2, float h,
                                         float& vn, float& in_, float& sn) {
    // k1
    float dv1 = mu1 * (i + ic - v);
    float di1 = -mu2 * i;
    float ds1 = sigm(v);
    // k2
    float v2 = fmaf(0.5f * h, dv1, v);
    float i2 = fmaf(0.5f * h, di1, i);
    float dv2 = mu1 * (i2 + ic - v2);
    float di2 = -mu2 * i2;
    float ds2 = sigm(v2);
    // k3
    float v3 = fmaf(0.5f * h, dv2, v);
    float i3 = fmaf(0.5f * h, di2, i);
    float dv3 = mu1 * (i3 + ic - v3);
    float di3 = -mu2 * i3;
    float ds3 = sigm(v3);
    // k4
    float v4 = fmaf(h, dv3, v);
    float i4 = fmaf(h, di3, i);
    float dv4 = mu1 * (i4 + ic - v4);
    float di4 = -mu2 * i4;
    float ds4 = sigm(v4);

    const float c = h * (1.0f / 6.0f);
    vn  = fmaf(c, dv1 + 2.0f * (dv2 + dv3) + dv4, v);
    in_ = fmaf(c, di1 + 2.0f * (di2 + di3) + di4, i);
    sn  = fmaf(c, ds1 + 2.0f * (ds2 + ds3) + ds4, s);
}

// order-preserving float<->uint maps
__device__ __forceinline__ unsigned f2ord(float x) {
    unsigned u = __float_as_uint(x);
    return (u & 0x80000000u) ? ~u : (u | 0x80000000u);
}
__device__ __forceinline__ float ord2f(unsigned o) {
    unsigned u = (o & 0x80000000u) ? (o & 0x7fffffffu) : ~o;
    return __uint_as_float(u);
}

__global__ __launch_bounds__(NT, 8)
void snn_kernel(const float* __restrict__ ic_g,     // [NN]
                const float* __restrict__ w,        // [NN, NN]
                const float* __restrict__ mu_g,     // [2]
                const float* __restrict__ v0_g,     // [NN]
                const float* __restrict__ i0_g,     // [NN]
                const float* __restrict__ s0_g,     // [NS, NN]
                const float* __restrict__ reset_s,  // [MAXSP, NS, NN]
                const int*   __restrict__ t1_p,     // scalar
                float* __restrict__ out_times,      // [NS, MAXSP]
                float* __restrict__ out_vals,       // [NS, MAXSP, NN, 3]
                float* __restrict__ out_marks)      // [NS, MAXSP, NN]
{
    const int smp = blockIdx.x;
    const int tid = threadIdx.x;          // 0..127
    const int na  = 2 * tid;              // even neuron
    // odd neuron = na + 1

    const float t1f = (float)(*t1_p);
    const float mu1 = mu_g[0];
    const float mu2 = mu_g[1];

    const float2 ic2 = ((const float2*)ic_g)[tid];
    float2 v2r = ((const float2*)v0_g)[tid];
    float2 i2r = ((const float2*)i0_g)[tid];
    float2 s2r = ((const float2*)(s0_g + (size_t)smp * NN))[tid];

    float va = v2r.x, vb = v2r.y;
    float ia = i2r.x, ib = i2r.y;
    float sa = s2r.x, sb = s2r.y;
    float t0 = 0.0f;

    // parity-buffered trigger cells (0 == "no trigger")
    __shared__ unsigned long long key_sh[2];
    __shared__ int                eidx_sh[2];
    __shared__ float              s_all[2][NN];  // s_prev published by crossers

    if (tid == 0) {
        key_sh[0] = key_sh[1] = 0ull;
        eidx_sh[0] = eidx_sh[1] = NN;
    }
    __syncthreads();

    #pragma unroll 1
    for (int k = 0; k < MAXSP; k++) {
        const float2 rs2 =
            ((const float2*)(reset_s + ((size_t)k * NS + smp) * NN))[tid];

        const float dt = (t1f - t0) * (1.0f / NSTEPS);
        bool  done = false;
        float tev  = t1f;
        bool  ema = false, emb = false;
        int   eidx = 0;

        if (dt > 0.0f) {
            #pragma unroll 1
            for (int st = 0; st < NSTEPS; st++) {
                float vna, ina, sna, vnb, inb, snb;
                rk4_step(va, ia, sa, ic2.x, mu1, mu2, dt, vna, ina, sna);
                rk4_step(vb, ib, sb, ic2.y, mu1, mu2, dt, vnb, inb, snb);

                const int p = st & 1;
                const bool ca = sna > 0.0f;
                const bool cb = snb > 0.0f;
                if (ca | cb) {
                    // rare: publish candidacy (pre-barrier, few threads)
                    if (ca) s_all[p][na]     = sa;
                    if (cb) s_all[p][na + 1] = sb;
                    float bsn; int bidx;
                    if (ca && (!cb || sna >= snb)) { bsn = sna; bidx = na; }
                    else                           { bsn = snb; bidx = na + 1; }
                    atomicMax(&key_sh[p],
                              ((unsigned long long)f2ord(bsn) << 8)
                              | (unsigned long long)(255 - bidx));
                    atomicMin(&eidx_sh[p], ca ? na : na + 1);
                }
                __syncthreads();
                const unsigned long long key = key_sh[p];

                if (key) {
                    // ---- trigger (once per round), block-uniform ----
                    ema  = ca; emb = cb;
                    eidx = eidx_sh[p];
                    const int   widx = 255 - (int)(key & 0xffull);
                    const float mval = ord2f((unsigned)(key >> 8));
                    const float msp  = s_all[p][widx];

                    float frac = msp / (msp - mval + 1e-12f);
                    frac = fminf(fmaxf(frac, 0.0f), 1.0f);
                    tev = t0 + (float)st * dt + frac * dt;
                    va += frac * (vna - va);  vb += frac * (vnb - vb);
                    ia += frac * (ina - ia);  ib += frac * (inb - ib);
                    sa += frac * (sna - sa);  sb += frac * (snb - sb);
                    done = true;

                    __syncthreads();          // all reads of cells complete
                    if (tid == 0) { key_sh[p] = 0ull; eidx_sh[p] = NN; }
                    // thread0's reset STS issues 2 instr after the barrier;
                    // any later publish to this cell is >100 instr away.
                    break;
                }
                va = vna; ia = ina; sa = sna;
                vb = vnb; ib = inb; sb = snb;
            }
        }

        // ---- outputs (pre-reset event state); tev = t1f if no trigger ----
        const size_t rowbase = ((size_t)smp * MAXSP + k) * NN;
        if (tid == 0) out_times[smp * MAXSP + k] = tev;
        {
            float2* vo = (float2*)(out_vals + rowbase * 3);
            vo[3 * tid + 0] = make_float2(va, ia);
            vo[3 * tid + 1] = make_float2(sa, vb);
            vo[3 * tid + 2] = make_float2(ib, sb);
            ((float2*)(out_marks + rowbase))[tid] =
                make_float2(ema ? 1.0f : 0.0f, emb ? 1.0f : 0.0f);
        }

        // ---- reset & carry ----
        float2 wr = make_float2(0.0f, 0.0f);
        if (done) wr = ((const float2*)(w + (size_t)eidx * NN))[tid];
        va -= ema ? V_RESET : 0.0f;
        vb -= emb ? V_RESET : 0.0f;
        ia += wr.x;
        ib += wr.y;
        sa  = fminf(ema ? rs2.x : sa, 0.0f);
        sb  = fminf(emb ? rs2.y : sb, 0.0f);
        t0 = tev;
    }
}

extern "C" void kernel_launch(void* const* d_in, const int* in_sizes, int n_in,
                              void* d_out, int out_size) {
    const float* ic      = (const float*)d_in[0];
    const float* w       = (const float*)d_in[1];
    const float* mu      = (const float*)d_in[2];
    const float* v0      = (const float*)d_in[3];
    const float* i0      = (const float*)d_in[4];
    const float* s0      = (const float*)d_in[5];
    const float* reset_s = (const float*)d_in[6];
    const int*   t1      = (const int*)d_in[7];

    float* out = (float*)d_out;
    float* out_times = out;                                    // NS*MAXSP
    float* out_vals  = out + (size_t)NS * MAXSP;               // NS*MAXSP*NN*3
    float* out_marks = out_vals + (size_t)NS * MAXSP * NN * 3; // NS*MAXSP*NN

    snn_kernel<<<NS, NT>>>(ic, w, mu, v0, i0, s0, reset_s, t1,
                           out_times, out_vals, out_marks);
}